// round 11
// baseline (speedup 1.0000x reference)
#include <cuda_runtime.h>
#include <cstdint>

#define BZ 8
#define NF 10000
#define DD 16
#define HH 512
#define WW 512
#define NPIX (BZ * HH * WW)
#define HWPIX (HH * WW)

#define TPB 256
#define SLOTS 32            // TPB/8 pixel-slots, 8 lanes each
#define CH 4                // independent pixel chains per thread
#define PPB (SLOTS * CH)    // 128 pixels per block

__global__ __launch_bounds__(TPB) void renderer_kernel(
    const float4* __restrict__ attrs,    // records of 12 float4, stride 192 B
    const float*  __restrict__ baryw,    // [BZ,H,W,3]
    const int*    __restrict__ tri,      // [BZ,H,W]
    float*        __restrict__ out)      // [BZ, D+1, H, W]
{
    __shared__ float stage[PPB * 20];    // stride 20: conflict-free, 16B-aligned rows

    const int tid  = threadIdx.x;
    const int slot = tid >> 3;           // 0..31
    const int j    = tid & 7;            // lane within pixel
    const int base = blockIdx.x * PPB;

    // ---- phase A: batch all index/weight loads (CH independent chains) ----
    int   ti[CH];
    float m [CH], w0[CH], w1[CH], w2[CH];
    #pragma unroll
    for (int c = 0; c < CH; c++) {
        int p = base + slot + c * SLOTS;
        int t = tri[p];
        bool fg = (t >= 0);
        ti[c] = fg ? t : 0;
        m[c]  = fg ? 1.0f : 0.0f;
        w0[c] = baryw[p * 3 + 0] * m[c];
        w1[c] = baryw[p * 3 + 1] * m[c];
        w2[c] = baryw[p * 3 + 2] * m[c];
    }

    // ---- phase B: issue all gathers back-to-back (max MLP) ----
    float4 A[CH], C[CH];
    #pragma unroll
    for (int c = 0; c < CH; c++) {
        const float4* rec = attrs + (size_t)ti[c] * 12;
        A[c] = rec[j];                       // lanes 0..7: v0q0-3, v1q0-3
        if (j < 4) C[c] = rec[8 + j];        // lanes 0..3: v2 quad j
    }

    // ---- phase C: interpolate + fold v1 partials via shfl ----
    #pragma unroll
    for (int c = 0; c < CH; c++) {
        float4 P;
        if (j < 4) {
            P.x = fmaf(w0[c], A[c].x, w2[c] * C[c].x);
            P.y = fmaf(w0[c], A[c].y, w2[c] * C[c].y);
            P.z = fmaf(w0[c], A[c].z, w2[c] * C[c].z);
            P.w = fmaf(w0[c], A[c].w, w2[c] * C[c].w);
        } else {
            P.x = w1[c] * A[c].x; P.y = w1[c] * A[c].y;
            P.z = w1[c] * A[c].z; P.w = w1[c] * A[c].w;
        }
        P.x += __shfl_xor_sync(0xffffffffu, P.x, 4);
        P.y += __shfl_xor_sync(0xffffffffu, P.y, 4);
        P.z += __shfl_xor_sync(0xffffffffu, P.z, 4);
        P.w += __shfl_xor_sync(0xffffffffu, P.w, 4);

        int sl = slot + c * SLOTS;
        if (j < 4)
            *(float4*)&stage[sl * 20 + 4 * j] = P;
        if (j == 0)
            stage[sl * 20 + 16] = m[c];
    }
    __syncthreads();

    // ---- phase D: store transpose — each STG warp-instruction writes 32
    // consecutive pixels of one channel = exactly one 128B line ----
    const int n   = base / HWPIX;            // 128 | HWPIX
    const int hw0 = base - n * HWPIX;
    float* ob = out + (size_t)n * (DD + 1) * HWPIX + hw0;

    const int px = tid & 127;                // pixel within block
    #pragma unroll
    for (int it = 0; it < 2; it++) {
        int q = (tid >> 7) + 2 * it;         // channel quad 0..3
        float4 v = *(const float4*)&stage[px * 20 + 4 * q];
        ob[(size_t)(4 * q + 0) * HWPIX + px] = v.x;
        ob[(size_t)(4 * q + 1) * HWPIX + px] = v.y;
        ob[(size_t)(4 * q + 2) * HWPIX + px] = v.z;
        ob[(size_t)(4 * q + 3) * HWPIX + px] = v.w;
    }
    if (tid < PPB)
        ob[(size_t)DD * HWPIX + tid] = stage[tid * 20 + 16];
}

extern "C" void kernel_launch(void* const* d_in, const int* in_sizes, int n_in,
                              void* d_out, int out_size) {
    const float4* attrs = (const float4*)d_in[0];
    const float*  baryw = (const float*)d_in[1];
    const int*    tri   = (const int*)d_in[2];
    float*        out   = (float*)d_out;

    renderer_kernel<<<NPIX / PPB, TPB>>>(attrs, baryw, tri, out);
}